// round 2
// baseline (speedup 1.0000x reference)
#include <cuda_runtime.h>

#define NQ     4096
#define MT     16384
#define DD     32
#define OUTD   16
#define KNB    5
#define EPSV   1e-6f

#define SPLIT  16
#define PPL    (MT / SPLIT)   // 1024 points per (lane, split)
#define CT     256            // points staged per chunk
#define CHUNKS (PPL / CT)     // 4
#define QPB    128            // queries per block (1 per lane)
#define CAP    96             // candidate slots per (query, split)
#define TS2    130            // u64 stride of point-pair rows (even => 16B align)
#define TSF    (TS2 * 2)      // float stride (260)

typedef unsigned long long u64;

// candidate lists: per (query, split), lane-private, no atomics needed
__device__ u64 g_cand[(size_t)NQ * SPLIT * CAP];
__device__ int g_cnt[NQ * SPLIT];

__device__ __forceinline__ u64 fma2(u64 a, u64 b, u64 c) {
    u64 d;
    asm("fma.rn.f32x2 %0, %1, %2, %3;" : "=l"(d) : "l"(a), "l"(b), "l"(c));
    return d;
}
__device__ __forceinline__ u64 add2(u64 a, u64 b) {
    u64 d;
    asm("add.rn.f32x2 %0, %1, %2;" : "=l"(d) : "l"(a), "l"(b));
    return d;
}
__device__ __forceinline__ u64 splat2(float f) {
    unsigned int u = __float_as_uint(f);
    return ((u64)u << 32) | (u64)u;
}
__device__ __forceinline__ float lo32(u64 v) { return __uint_as_float((unsigned int)v); }
__device__ __forceinline__ float hi32(u64 v) { return __uint_as_float((unsigned int)(v >> 32)); }

// predicated push: if (s < v4 && ptr < lim) { *ptr = (idx,s); ptr += 8; }  — no branch
__device__ __forceinline__ void push_cand(u64& ptr, u64 lim, float s, float v4, int idx) {
    unsigned int sb = __float_as_uint(s);
    asm volatile(
        "{\n\t"
        ".reg .pred a, b;\n\t"
        "setp.lt.f32 a, %1, %2;\n\t"
        "setp.lt.u64 b, %0, %3;\n\t"
        "and.pred a, a, b;\n\t"
        "@a st.global.v2.b32 [%0], {%4, %5};\n\t"
        "@a add.u64 %0, %0, 8;\n\t"
        "}"
        : "+l"(ptr)
        : "f"(s), "f"(v4), "l"(lim), "r"(sb), "r"(idx)
        : "memory");
}

// branchless exact top-5-smallest value network (9 FMNMX); V0<=..<=V4 invariant
#define NET5(s) do {                         \
    V4 = fminf(fmaxf((s), V3), V4);          \
    V3 = fminf(fmaxf((s), V2), V3);          \
    V2 = fminf(fmaxf((s), V1), V2);          \
    V1 = fminf(fmaxf((s), V0), V1);          \
    V0 = fminf((s), V0);                     \
} while (0)

__global__ void __launch_bounds__(QPB, 4) idw_scan_kernel(
    const float* __restrict__ xg,    // [NQ, DD]
    const float* __restrict__ txg,   // [MT, DD]
    const float* __restrict__ wg)    // [DD]
{
    __shared__ float sinv[DD];
    __shared__ __align__(16) u64 tsT2[DD * TS2];   // scaled points, f32x2 pairs, [d][pair]
    __shared__ __align__(16) u64 tn2[CT / 2];      // per-pair squared norms

    const int tid = threadIdx.x;
    const int qb  = blockIdx.x >> 4;     // 0..31
    const int sp  = blockIdx.x & 15;     // 0..15
    const int q   = qb * QPB + tid;      // this lane's query

    if (tid < DD) sinv[tid] = expf(-wg[tid]);
    __syncthreads();

    // scaled query as f32x2 splats, in registers (64 regs)
    u64 q2[DD];
    {
        const float4* xr = (const float4*)(xg + (size_t)q * DD);
        #pragma unroll
        for (int i = 0; i < 8; i++) {
            float4 v = xr[i];
            q2[4 * i + 0] = splat2(v.x * sinv[4 * i + 0]);
            q2[4 * i + 1] = splat2(v.y * sinv[4 * i + 1]);
            q2[4 * i + 2] = splat2(v.z * sinv[4 * i + 2]);
            q2[4 * i + 3] = splat2(v.w * sinv[4 * i + 3]);
        }
    }

    float V0 = 3.0e38f, V1 = 3.0e38f, V2 = 3.0e38f, V3 = 3.0e38f, V4 = 3.0e38f;

    u64 ptr  = (u64)(&g_cand[((size_t)q * SPLIT + sp) * CAP]);
    const u64 base = ptr;
    const u64 lim  = ptr + (u64)CAP * 8;

    const u64 M2 = 0xC0000000C0000000ULL;   // (-2.0f, -2.0f)
    const int pbase0 = sp * PPL;

    #pragma unroll 1
    for (int c = 0; c < CHUNKS; c++) {
        const int pbase = pbase0 + c * CT;
        __syncthreads();

        // stage scaled train chunk transposed [d][p] (float view, stride TSF)
        {
            float* fv = (float*)tsT2;
            const int d  = tid & 31;
            const int r0 = (tid >> 5) * 64;   // 4 row-groups of 64 points
            const float si = sinv[d];
            const float* src = txg + (size_t)pbase * DD + d;
            #pragma unroll 16
            for (int k = 0; k < 64; k++) {
                fv[d * TSF + r0 + k] = src[(size_t)(r0 + k) * DD] * si;
            }
        }
        __syncthreads();

        // per-pair squared norms
        {
            const float* fv = (const float*)tsT2;
            float a = 0.f, b = 0.f;
            #pragma unroll
            for (int d = 0; d < DD; d++) {
                float2 p = *(const float2*)&fv[d * TSF + 2 * tid];
                a = fmaf(p.x, p.x, a);
                b = fmaf(p.y, p.y, b);
            }
            unsigned int ua = __float_as_uint(a);
            unsigned int ub = __float_as_uint(b);
            tn2[tid] = ((u64)ub << 32) | (u64)ua;
        }
        __syncthreads();

        // main scan: 4 points per group, broadcast LDS.128, f32x2 FMA
        #pragma unroll 1
        for (int g = 0; g < CT / 4; g++) {
            u64 a0 = 0, a1 = 0, a2 = 0, a3 = 0;
            #pragma unroll
            for (int d = 0; d < DD; d += 2) {
                ulonglong2 Pa = *(const ulonglong2*)&tsT2[d * TS2 + 2 * g];
                ulonglong2 Pb = *(const ulonglong2*)&tsT2[(d + 1) * TS2 + 2 * g];
                a0 = fma2(q2[d],     Pa.x, a0);
                a2 = fma2(q2[d],     Pa.y, a2);
                a1 = fma2(q2[d + 1], Pb.x, a1);
                a3 = fma2(q2[d + 1], Pb.y, a3);
            }
            u64 A = add2(a0, a1);
            u64 B = add2(a2, a3);
            ulonglong2 T = *(const ulonglong2*)&tn2[2 * g];
            u64 s01 = fma2(A, M2, T.x);      // tn - 2*dot (pair 0)
            u64 s23 = fma2(B, M2, T.y);      // (pair 1)
            float s0 = lo32(s01), s1 = hi32(s01);
            float s2 = lo32(s23), s3 = hi32(s23);

            const float v4g = V4;            // stale-per-group threshold: superset pushes, sound
            const int p0 = pbase + 4 * g;
            push_cand(ptr, lim, s0, v4g, p0 + 0);
            push_cand(ptr, lim, s1, v4g, p0 + 1);
            push_cand(ptr, lim, s2, v4g, p0 + 2);
            push_cand(ptr, lim, s3, v4g, p0 + 3);

            NET5(s0); NET5(s1); NET5(s2); NET5(s3);
        }
    }

    g_cnt[q * SPLIT + sp] = (int)((ptr - base) >> 3);
}

// branchy sorted insert is fine here: serial per-thread merge of ~500 candidates
#define INS5(V, I, s, g) do {                                                  \
    if ((s) < V[4]) {                                                          \
        V[4] = (s); I[4] = (g);                                                \
        if (V[4] < V[3]) { float t_=V[3]; V[3]=V[4]; V[4]=t_; int u_=I[3]; I[3]=I[4]; I[4]=u_; } \
        if (V[3] < V[2]) { float t_=V[2]; V[2]=V[3]; V[3]=t_; int u_=I[2]; I[2]=I[3]; I[3]=u_; } \
        if (V[2] < V[1]) { float t_=V[1]; V[1]=V[2]; V[2]=t_; int u_=I[1]; I[1]=I[2]; I[2]=u_; } \
        if (V[1] < V[0]) { float t_=V[0]; V[0]=V[1]; V[1]=t_; int u_=I[0]; I[0]=I[1]; I[1]=u_; } \
    } } while (0)

__global__ void idw_final_kernel(
    const float* __restrict__ xg,    // [NQ, DD]
    const float* __restrict__ tyg,   // [MT, OUTD]
    const float* __restrict__ wg,    // [DD]
    float* __restrict__ outg)        // [NQ, OUTD]
{
    __shared__ float sinv[DD];
    const int tid = threadIdx.x;
    if (tid < DD) sinv[tid] = expf(-wg[tid]);
    __syncthreads();

    const int q = blockIdx.x * 32 + tid;
    if (q >= NQ) return;

    // query squared norm (scaled)
    float qn = 0.f;
    {
        const float4* xr = (const float4*)(xg + (size_t)q * DD);
        #pragma unroll
        for (int i = 0; i < 8; i++) {
            float4 v = xr[i];
            float f0 = v.x * sinv[4 * i + 0];
            float f1 = v.y * sinv[4 * i + 1];
            float f2 = v.z * sinv[4 * i + 2];
            float f3 = v.w * sinv[4 * i + 3];
            qn = fmaf(f0, f0, qn); qn = fmaf(f1, f1, qn);
            qn = fmaf(f2, f2, qn); qn = fmaf(f3, f3, qn);
        }
    }

    // exact top-5 merge over all pushed candidates
    float bv[KNB]; int bi[KNB];
    #pragma unroll
    for (int k = 0; k < KNB; k++) { bv[k] = 3.0e38f; bi[k] = 0; }

    for (int sp = 0; sp < SPLIT; sp++) {
        const int slot = q * SPLIT + sp;
        const int cnt = g_cnt[slot];
        const u64* lst = &g_cand[(size_t)slot * CAP];
        for (int i = 0; i < cnt; i++) {
            u64 e = lst[i];
            float s = __uint_as_float((unsigned int)e);
            int idx = (int)(e >> 32);
            INS5(bv, bi, s, idx);
        }
    }

    // weighted output from exact 5 nearest
    float o[OUTD];
    #pragma unroll
    for (int k = 0; k < OUTD; k++) o[k] = 0.f;
    float wsum = 0.f;

    #pragma unroll
    for (int k = 0; k < KNB; k++) {
        float sq = qn + bv[k];
        float dinv = rsqrtf(fmaxf(sq, 0.f) + EPSV);
        wsum += dinv;
        const float4* yr = (const float4*)(tyg + (size_t)bi[k] * OUTD);
        #pragma unroll
        for (int j = 0; j < 4; j++) {
            float4 y = yr[j];
            o[4 * j + 0] = fmaf(dinv, y.x, o[4 * j + 0]);
            o[4 * j + 1] = fmaf(dinv, y.y, o[4 * j + 1]);
            o[4 * j + 2] = fmaf(dinv, y.z, o[4 * j + 2]);
            o[4 * j + 3] = fmaf(dinv, y.w, o[4 * j + 3]);
        }
    }
    float wi = 1.f / wsum;
    float4* dst = (float4*)(outg + (size_t)q * OUTD);
    #pragma unroll
    for (int j = 0; j < 4; j++) {
        float4 r;
        r.x = o[4 * j + 0] * wi; r.y = o[4 * j + 1] * wi;
        r.z = o[4 * j + 2] * wi; r.w = o[4 * j + 3] * wi;
        dst[j] = r;
    }
}

extern "C" void kernel_launch(void* const* d_in, const int* in_sizes, int n_in,
                              void* d_out, int out_size)
{
    const float *xg = nullptr, *txg = nullptr, *tyg = nullptr, *wg = nullptr;
    for (int i = 0; i < n_in; i++) {
        switch (in_sizes[i]) {
            case NQ * DD:   xg  = (const float*)d_in[i]; break;  // 131072
            case MT * DD:   txg = (const float*)d_in[i]; break;  // 524288
            case MT * OUTD: tyg = (const float*)d_in[i]; break;  // 262144
            case DD:        wg  = (const float*)d_in[i]; break;  // 32
        }
    }
    float* outg = (float*)d_out;

    idw_scan_kernel<<< (NQ / QPB) * SPLIT, QPB >>>(xg, txg, wg);
    idw_final_kernel<<< NQ / 32, 32 >>>(xg, tyg, wg, outg);
}

// round 3
// speedup vs baseline: 1.5865x; 1.5865x over previous
#include <cuda_runtime.h>

#define NQ     4096
#define MT     16384
#define DD     32
#define OUTD   16
#define KNB    5
#define EPSV   1e-6f

#define SPLIT  32
#define PPL    (MT / SPLIT)   // 512 points per (lane, split)
#define CT     256            // points staged per chunk
#define CHUNKS (PPL / CT)     // 2
#define QPB    128            // queries per block (1 per lane)
#define CAPR   80             // pair-records per (query, split)
#define TS2    130            // u64 stride of point-pair rows (16B-aligned rows)
#define TSF    (TS2 * 2)      // float stride (260)

typedef unsigned long long u64;
typedef unsigned int u32;

// candidate pair-records: {s_lo_bits, s_hi_bits, idx, pad}, lane-private streams
__device__ uint4 g_cand[(size_t)NQ * SPLIT * CAPR];
__device__ int   g_cnt[NQ * SPLIT];

__device__ __forceinline__ u64 fma2(u64 a, u64 b, u64 c) {
    u64 d;
    asm("fma.rn.f32x2 %0, %1, %2, %3;" : "=l"(d) : "l"(a), "l"(b), "l"(c));
    return d;
}
__device__ __forceinline__ u64 add2(u64 a, u64 b) {
    u64 d;
    asm("add.rn.f32x2 %0, %1, %2;" : "=l"(d) : "l"(a), "l"(b));
    return d;
}
__device__ __forceinline__ u64 splat2(float f) {
    u32 u = __float_as_uint(f);
    return ((u64)u << 32) | (u64)u;
}
__device__ __forceinline__ float lo32(u64 v) { return __uint_as_float((u32)v); }
__device__ __forceinline__ float hi32(u64 v) { return __uint_as_float((u32)(v >> 32)); }

// predicated pair push: if ((slo<v4 || shi<v4) && ptr<lim) { *ptr = {slo,shi,idx,0}; ptr+=16; }
__device__ __forceinline__ void push_pair(u64& ptr, u64 lim,
                                          float slo, float shi, float v4, int idx) {
    u32 a = __float_as_uint(slo);
    u32 b = __float_as_uint(shi);
    asm volatile(
        "{\n\t"
        ".reg .pred p, q, r;\n\t"
        "setp.lt.f32 p, %1, %3;\n\t"
        "setp.lt.f32 q, %2, %3;\n\t"
        "or.pred p, p, q;\n\t"
        "setp.lt.u64 r, %0, %4;\n\t"
        "and.pred p, p, r;\n\t"
        "@p st.global.v4.b32 [%0], {%5, %6, %7, %7};\n\t"
        "@p add.u64 %0, %0, 16;\n\t"
        "}"
        : "+l"(ptr)
        : "f"(slo), "f"(shi), "f"(v4), "l"(lim), "r"(a), "r"(b), "r"(idx)
        : "memory");
}

// branchless exact running top-5-smallest (values only); V0<=..<=V4
#define NET5(s) do {                         \
    V4 = fminf(fmaxf((s), V3), V4);          \
    V3 = fminf(fmaxf((s), V2), V3);          \
    V2 = fminf(fmaxf((s), V1), V2);          \
    V1 = fminf(fmaxf((s), V0), V1);          \
    V0 = fminf((s), V0);                     \
} while (0)

__global__ void __launch_bounds__(QPB, 4) idw_scan_kernel(
    const float* __restrict__ xg,    // [NQ, DD]
    const float* __restrict__ txg,   // [MT, DD]
    const float* __restrict__ wg)    // [DD]
{
    __shared__ float sinv[DD];
    __shared__ __align__(16) u64 tsT2[DD * TS2];   // scaled points, f32x2 pairs, [d][pair]
    __shared__ __align__(16) u64 tn2[CT / 2];      // per-pair squared norms

    const int tid = threadIdx.x;
    const int qb  = blockIdx.x >> 5;     // 0..31
    const int sp  = blockIdx.x & 31;     // 0..31
    const int q   = qb * QPB + tid;

    if (tid < DD) sinv[tid] = expf(-wg[tid]);
    __syncthreads();

    // scaled query as f32x2 splats, in registers
    u64 q2[DD];
    {
        const float4* xr = (const float4*)(xg + (size_t)q * DD);
        #pragma unroll
        for (int i = 0; i < 8; i++) {
            float4 v = xr[i];
            q2[4 * i + 0] = splat2(v.x * sinv[4 * i + 0]);
            q2[4 * i + 1] = splat2(v.y * sinv[4 * i + 1]);
            q2[4 * i + 2] = splat2(v.z * sinv[4 * i + 2]);
            q2[4 * i + 3] = splat2(v.w * sinv[4 * i + 3]);
        }
    }

    float V0 = 3.0e38f, V1 = 3.0e38f, V2 = 3.0e38f, V3 = 3.0e38f, V4 = 3.0e38f;

    u64 ptr  = (u64)(&g_cand[((size_t)q * SPLIT + sp) * CAPR]);
    const u64 base = ptr;
    const u64 lim  = ptr + (u64)CAPR * 16;

    const u64 M2 = 0xC0000000C0000000ULL;   // (-2.0f, -2.0f)
    const int pbase0 = sp * PPL;

    #pragma unroll 1
    for (int c = 0; c < CHUNKS; c++) {
        const int pbase = pbase0 + c * CT;
        __syncthreads();

        // stage scaled train chunk transposed [d][p]
        {
            float* fv = (float*)tsT2;
            const int d  = tid & 31;
            const int r0 = (tid >> 5) * 64;
            const float si = sinv[d];
            const float* src = txg + (size_t)pbase * DD + d;
            #pragma unroll 16
            for (int k = 0; k < 64; k++) {
                fv[d * TSF + r0 + k] = src[(size_t)(r0 + k) * DD] * si;
            }
        }
        __syncthreads();

        // per-pair squared norms (2 points per thread)
        {
            const float* fv = (const float*)tsT2;
            float a = 0.f, b = 0.f;
            #pragma unroll
            for (int d = 0; d < DD; d++) {
                float2 p = *(const float2*)&fv[d * TSF + 2 * tid];
                a = fmaf(p.x, p.x, a);
                b = fmaf(p.y, p.y, b);
            }
            tn2[tid] = ((u64)__float_as_uint(b) << 32) | (u64)__float_as_uint(a);
        }
        __syncthreads();

        // main scan: 8 points per group, broadcast LDS.128, f32x2 FMA
        #pragma unroll 1
        for (int g = 0; g < CT / 8; g++) {
            u64 acc[8];
            #pragma unroll
            for (int j = 0; j < 8; j++) acc[j] = 0ULL;

            const u64* gbase = tsT2 + 4 * g;
            #pragma unroll
            for (int d = 0; d < DD; d += 2) {
                ulonglong2 A0 = *(const ulonglong2*)(gbase + d * TS2);
                ulonglong2 A1 = *(const ulonglong2*)(gbase + d * TS2 + 2);
                ulonglong2 B0 = *(const ulonglong2*)(gbase + (d + 1) * TS2);
                ulonglong2 B1 = *(const ulonglong2*)(gbase + (d + 1) * TS2 + 2);
                acc[0] = fma2(q2[d],     A0.x, acc[0]);
                acc[1] = fma2(q2[d],     A0.y, acc[1]);
                acc[2] = fma2(q2[d],     A1.x, acc[2]);
                acc[3] = fma2(q2[d],     A1.y, acc[3]);
                acc[4] = fma2(q2[d + 1], B0.x, acc[4]);
                acc[5] = fma2(q2[d + 1], B0.y, acc[5]);
                acc[6] = fma2(q2[d + 1], B1.x, acc[6]);
                acc[7] = fma2(q2[d + 1], B1.y, acc[7]);
            }
            u64 D0 = add2(acc[0], acc[4]);
            u64 D1 = add2(acc[1], acc[5]);
            u64 D2 = add2(acc[2], acc[6]);
            u64 D3 = add2(acc[3], acc[7]);

            ulonglong2 T0 = *(const ulonglong2*)&tn2[4 * g];
            ulonglong2 T1 = *(const ulonglong2*)&tn2[4 * g + 2];
            u64 s01 = fma2(D0, M2, T0.x);
            u64 s23 = fma2(D1, M2, T0.y);
            u64 s45 = fma2(D2, M2, T1.x);
            u64 s67 = fma2(D3, M2, T1.y);

            float s0 = lo32(s01), s1 = hi32(s01);
            float s2 = lo32(s23), s3 = hi32(s23);
            float s4 = lo32(s45), s5 = hi32(s45);
            float s6 = lo32(s67), s7 = hi32(s67);

            const float v4s = V4;     // snapshot threshold: superset pushes, sound
            const int p0 = pbase + 8 * g;
            push_pair(ptr, lim, s0, s1, v4s, p0 + 0);
            push_pair(ptr, lim, s2, s3, v4s, p0 + 2);
            push_pair(ptr, lim, s4, s5, v4s, p0 + 4);
            push_pair(ptr, lim, s6, s7, v4s, p0 + 6);

            NET5(s0); NET5(s1); NET5(s2); NET5(s3);
            NET5(s4); NET5(s5); NET5(s6); NET5(s7);
        }
    }

    g_cnt[q * SPLIT + sp] = (int)((ptr - base) >> 4);
}

// branchy sorted insert (rare-taken in practice)
#define INS5(V, I, s, g) do {                                                  \
    if ((s) < V[4]) {                                                          \
        V[4] = (s); I[4] = (g);                                                \
        if (V[4] < V[3]) { float t_=V[3]; V[3]=V[4]; V[4]=t_; int u_=I[3]; I[3]=I[4]; I[4]=u_; } \
        if (V[3] < V[2]) { float t_=V[2]; V[2]=V[3]; V[3]=t_; int u_=I[2]; I[2]=I[3]; I[3]=u_; } \
        if (V[2] < V[1]) { float t_=V[1]; V[1]=V[2]; V[2]=t_; int u_=I[1]; I[1]=I[2]; I[2]=u_; } \
        if (V[1] < V[0]) { float t_=V[0]; V[0]=V[1]; V[1]=t_; int u_=I[0]; I[0]=I[1]; I[1]=u_; } \
    } } while (0)

__device__ __forceinline__ u32 mono32(float f) {
    u32 b = __float_as_uint(f);
    return b ^ ((u32)((int)b >> 31) | 0x80000000u);
}

__global__ void __launch_bounds__(256) idw_final_kernel(
    const float* __restrict__ xg,    // [NQ, DD]
    const float* __restrict__ tyg,   // [MT, OUTD]
    const float* __restrict__ wg,    // [DD]
    float* __restrict__ outg)        // [NQ, OUTD]
{
    __shared__ float sinv[DD];
    const int tid  = threadIdx.x;
    const int lane = tid & 31;
    const int w    = tid >> 5;

    if (tid < DD) sinv[tid] = expf(-wg[tid]);
    __syncthreads();

    const int q = blockIdx.x * 8 + w;    // one warp per query
    const unsigned FULL = 0xFFFFFFFFu;

    // lane-local top-5 over strided records
    float bv[KNB]; int bi[KNB];
    #pragma unroll
    for (int k = 0; k < KNB; k++) { bv[k] = 3.0e38f; bi[k] = 0; }

    #pragma unroll 1
    for (int sp = 0; sp < SPLIT; sp++) {
        const int slot = q * SPLIT + sp;
        const int cnt = g_cnt[slot];
        const uint4* lst = &g_cand[(size_t)slot * CAPR];
        for (int i = lane; i < cnt; i += 32) {
            uint4 r = lst[i];
            float s0 = __uint_as_float(r.x);
            float s1 = __uint_as_float(r.y);
            int p = (int)r.z;
            INS5(bv, bi, s0, p);
            INS5(bv, bi, s1, p + 1);
        }
    }

    // exact warp top-5 via 5 rounds of arg-min
    float ts[KNB]; int ti[KNB];
    float cur = bv[0]; int curi = bi[0];
    #pragma unroll
    for (int r = 0; r < KNB; r++) {
        u32 key = mono32(cur);
        u32 m = __reduce_min_sync(FULL, key);
        unsigned mask = __ballot_sync(FULL, key == m);
        int leader = __ffs(mask) - 1;
        ts[r] = __shfl_sync(FULL, cur, leader);
        ti[r] = __shfl_sync(FULL, curi, leader);
        if (lane == leader) {
            bv[0]=bv[1]; bi[0]=bi[1];
            bv[1]=bv[2]; bi[1]=bi[2];
            bv[2]=bv[3]; bi[2]=bi[3];
            bv[3]=bv[4]; bi[3]=bi[4];
            bv[4]=3.0e38f; bi[4]=0;
            cur = bv[0]; curi = bi[0];
        }
    }

    // scaled query norm (lane d), warp-sum
    float xv = xg[(size_t)q * DD + lane] * sinv[lane];
    float qn = xv * xv;
    #pragma unroll
    for (int o = 16; o > 0; o >>= 1) qn += __shfl_xor_sync(FULL, qn, o);

    float dv[KNB], wsum = 0.f;
    #pragma unroll
    for (int k = 0; k < KNB; k++) {
        float sq = qn + ts[k];
        dv[k] = rsqrtf(fmaxf(sq, 0.f) + EPSV);
        wsum += dv[k];
    }
    const float wi = 1.f / wsum;

    if (lane < OUTD) {
        float o = 0.f;
        #pragma unroll
        for (int k = 0; k < KNB; k++)
            o = fmaf(dv[k], tyg[(size_t)ti[k] * OUTD + lane], o);
        outg[(size_t)q * OUTD + lane] = o * wi;
    }
}

extern "C" void kernel_launch(void* const* d_in, const int* in_sizes, int n_in,
                              void* d_out, int out_size)
{
    const float *xg = nullptr, *txg = nullptr, *tyg = nullptr, *wg = nullptr;
    for (int i = 0; i < n_in; i++) {
        switch (in_sizes[i]) {
            case NQ * DD:   xg  = (const float*)d_in[i]; break;  // 131072
            case MT * DD:   txg = (const float*)d_in[i]; break;  // 524288
            case MT * OUTD: tyg = (const float*)d_in[i]; break;  // 262144
            case DD:        wg  = (const float*)d_in[i]; break;  // 32
        }
    }
    float* outg = (float*)d_out;

    idw_scan_kernel<<< (NQ / QPB) * SPLIT, QPB >>>(xg, txg, wg);
    idw_final_kernel<<< NQ / 8, 256 >>>(xg, tyg, wg, outg);
}